// round 3
// baseline (speedup 1.0000x reference)
#include <cuda_runtime.h>
#include <cuda_fp16.h>
#include <cstdint>

#define N_NODES 4096
#define T_STEPS 64
#define H_DIM   128
#define DIN_    131
#define GIN_    132

// ---------------- static device workspace (no runtime allocation allowed) ----------
__device__ __half d_Ah[(size_t)N_NODES * N_NODES];   // row-normalized A, fp16 (33.5 MB)
__device__ float  d_Dfac[N_NODES];                   // D/(D+1e-8)
__device__ __half d_U16[N_NODES * 192];              // [n][c*64+t], c = m,tf,tj
__device__ __half d_P1[N_NODES * 192];               // Anorm @ U
__device__ __half d_P2[N_NODES * 192];               // Anorm @ P1
__device__ __half d_S[N_NODES * 384];                // [h | G1 | G2] fp16
__device__ __half d_X[N_NODES * 256];                // [msg | h] fp16
__device__ float  d_hst[N_NODES * H_DIM];            // carried state fp32 (exact)
__device__ float  d_M4[(size_t)N_NODES * 512];       // S @ Wcat
__device__ float  d_GG[(size_t)N_NODES * 768];       // [gi_msg | gh]
__device__ __half d_Wcat[384 * 512];                 // folded Cheb weights (h part)
__device__ float  d_WuC[3 * 3 * 4 * H_DIM];          // folded Cheb weights (u part)
__device__ __half d_Wihm[128 * 384];                 // W_ih[:, :128]^T
__device__ __half d_Whh[128 * 384];                  // W_hh^T

// ---------------- prep kernels ----------------
__global__ void __launch_bounds__(256) rownorm_kernel(const float* __restrict__ A) {
    int n = blockIdx.x;
    const float* row = A + (size_t)n * N_NODES;
    float s = 0.f;
    for (int j = threadIdx.x; j < N_NODES; j += 256) s += row[j];
    __shared__ float red[256];
    red[threadIdx.x] = s;
    __syncthreads();
    for (int o = 128; o > 0; o >>= 1) {
        if (threadIdx.x < o) red[threadIdx.x] += red[threadIdx.x + o];
        __syncthreads();
    }
    float D = red[0];
    float Dinv = (D > 0.f) ? (1.0f / D) : 0.f;
    if (threadIdx.x == 0) d_Dfac[n] = D / (D + 1e-8f);
    __half* dst = d_Ah + (size_t)n * N_NODES;
    for (int j = threadIdx.x; j < N_NODES; j += 256) dst[j] = __float2half(row[j] * Dinv);
}

__global__ void __launch_bounds__(256) build_u_kernel(const float* __restrict__ m,
                                                      const float* __restrict__ tf,
                                                      const float* __restrict__ tj) {
    int i = blockIdx.x * 256 + threadIdx.x;
    if (i >= N_NODES * T_STEPS) return;
    int n = i / T_STEPS, t = i % T_STEPS;
    d_U16[n * 192 + t]       = __float2half(m[i]);
    d_U16[n * 192 + 64 + t]  = __float2half(tf[i]);
    d_U16[n * 192 + 128 + t] = __float2half(tj[i]);
}

// W_msg layout: [4][3][131][128] : ((p*3+k)*131 + d)*128 + j
__global__ void __launch_bounds__(256) build_w_kernel(const float* __restrict__ W_msg,
                                                      const float* __restrict__ W_ih,
                                                      const float* __restrict__ W_hh) {
    int i = blockIdx.x * 256 + threadIdx.x;
    const int NWCAT = 384 * 512;
    const int NWUC  = 3 * 3 * 4 * 128;
    const int NWI   = 128 * 384;
    if (i < NWCAT) {
        int d = i >> 9, q = i & 511;
        int p = q >> 7, j = q & 127;
        int kc = d >> 7, c = d & 127;
        float v;
        if (kc == 0)      v = W_msg[((p*3+0)*DIN_ + c)*128 + j] - W_msg[((p*3+2)*DIN_ + c)*128 + j];
        else if (kc == 1) v = W_msg[((p*3+1)*DIN_ + c)*128 + j];
        else              v = 2.f * W_msg[((p*3+2)*DIN_ + c)*128 + j];
        d_Wcat[d * 512 + q] = __float2half(v);
    } else if (i < NWCAT + NWUC) {
        int r = i - NWCAT;
        int j = r & 127;
        int p = (r >> 7) & 3;
        int t2 = r >> 9;          // 0..8 = c*3 + which
        int which = t2 % 3;
        int c = t2 / 3;
        int dd = 128 + c;
        float v;
        if (which == 0)      v = W_msg[((p*3+0)*DIN_ + dd)*128 + j] - W_msg[((p*3+2)*DIN_ + dd)*128 + j];
        else if (which == 1) v = W_msg[((p*3+1)*DIN_ + dd)*128 + j];
        else                 v = 2.f * W_msg[((p*3+2)*DIN_ + dd)*128 + j];
        d_WuC[r] = v;
    } else if (i < NWCAT + NWUC + NWI) {
        int r = i - (NWCAT + NWUC);
        int d = r / 384, c = r % 384;          // Wihm[d][c] = W_ih[c][d]
        d_Wihm[r] = __float2half(W_ih[(size_t)c * GIN_ + d]);
    } else if (i < NWCAT + NWUC + 2 * NWI) {
        int r = i - (NWCAT + NWUC + NWI);
        int d = r / 384, c = r % 384;          // Whh[d][c] = W_hh[c][d]
        d_Whh[r] = __float2half(W_hh[(size_t)c * 128 + d]);
    }
}

__global__ void __launch_bounds__(256) init_kernel() {
    int i = blockIdx.x * 256 + threadIdx.x;
    if (i >= N_NODES * H_DIM) return;
    int n = i >> 7, j = i & 127;
    d_hst[i] = 0.f;
    d_S[n * 384 + j] = __float2half(0.f);
    d_X[n * 256 + 128 + j] = __float2half(0.f);
}

// ---------------- fp16 tensor-core GEMM: C[M,Nc] = A[M,K] @ B[K,Nc], fp32 accum ----
// BM=BN=64, BK=32, 128 threads (4 warps, each 32x32 subtile).
template <bool HALF_OUT>
__global__ void __launch_bounds__(128) gemm_tc(const __half* __restrict__ A,
                                               const __half* __restrict__ B,
                                               void* __restrict__ Cv,
                                               int M, int Nc, int K,
                                               int lda, int ldb, int ldc) {
    __shared__ __half sA[64][40];
    __shared__ __half sB[64][40];   // transposed: sB[n][k]
    int tid = threadIdx.x;
    int lane = tid & 31, w = tid >> 5;
    int wm = w >> 1, wn = w & 1;
    int g = lane >> 2, tig = lane & 3;
    int row0 = blockIdx.y * 64, col0 = blockIdx.x * 64;

    float acc[2][4][4];
#pragma unroll
    for (int a = 0; a < 2; a++)
#pragma unroll
        for (int b = 0; b < 4; b++)
#pragma unroll
            for (int c = 0; c < 4; c++) acc[a][b][c] = 0.f;

    int ar = tid >> 1, ac = (tid & 1) * 16;   // A: 64 rows x 32 cols, 16 halves/thread
    int br = tid >> 2, bc = (tid & 3) * 16;   // B: 32 rows x 64 cols

    for (int k0 = 0; k0 < K; k0 += 32) {
        const uint4* ga = (const uint4*)(A + (size_t)(row0 + ar) * lda + k0 + ac);
        uint4 av0 = ga[0], av1 = ga[1];
        *(uint4*)&sA[ar][ac]     = av0;
        *(uint4*)&sA[ar][ac + 8] = av1;

        const uint4* gb = (const uint4*)(B + (size_t)(k0 + br) * ldb + col0 + bc);
        uint4 bv0 = gb[0], bv1 = gb[1];
        __half tmp[16];
        *(uint4*)&tmp[0] = bv0;
        *(uint4*)&tmp[8] = bv1;
#pragma unroll
        for (int i = 0; i < 16; i++) sB[bc + i][br] = tmp[i];
        __syncthreads();

#pragma unroll
        for (int s = 0; s < 32; s += 16) {
            uint32_t a_[2][4], b_[4][2];
#pragma unroll
            for (int ms = 0; ms < 2; ms++) {
                int rm = wm * 32 + ms * 16;
                a_[ms][0] = *(const uint32_t*)&sA[rm + g][s + tig * 2];
                a_[ms][1] = *(const uint32_t*)&sA[rm + g + 8][s + tig * 2];
                a_[ms][2] = *(const uint32_t*)&sA[rm + g][s + tig * 2 + 8];
                a_[ms][3] = *(const uint32_t*)&sA[rm + g + 8][s + tig * 2 + 8];
            }
#pragma unroll
            for (int ns = 0; ns < 4; ns++) {
                int cb = wn * 32 + ns * 8 + g;
                b_[ns][0] = *(const uint32_t*)&sB[cb][s + tig * 2];
                b_[ns][1] = *(const uint32_t*)&sB[cb][s + tig * 2 + 8];
            }
#pragma unroll
            for (int ms = 0; ms < 2; ms++)
#pragma unroll
                for (int ns = 0; ns < 4; ns++)
                    asm volatile(
                        "mma.sync.aligned.m16n8k16.row.col.f32.f16.f16.f32 "
                        "{%0,%1,%2,%3},{%4,%5,%6,%7},{%8,%9},{%0,%1,%2,%3};\n"
                        : "+f"(acc[ms][ns][0]), "+f"(acc[ms][ns][1]),
                          "+f"(acc[ms][ns][2]), "+f"(acc[ms][ns][3])
                        : "r"(a_[ms][0]), "r"(a_[ms][1]), "r"(a_[ms][2]), "r"(a_[ms][3]),
                          "r"(b_[ns][0]), "r"(b_[ns][1]));
        }
        __syncthreads();
    }

#pragma unroll
    for (int ms = 0; ms < 2; ms++) {
        int r0 = row0 + wm * 32 + ms * 16 + g;
#pragma unroll
        for (int ns = 0; ns < 4; ns++) {
            int c = col0 + wn * 32 + ns * 8 + tig * 2;
            if (HALF_OUT) {
                __half* C = (__half*)Cv;
                C[(size_t)r0 * ldc + c]           = __float2half(acc[ms][ns][0]);
                C[(size_t)r0 * ldc + c + 1]       = __float2half(acc[ms][ns][1]);
                C[(size_t)(r0 + 8) * ldc + c]     = __float2half(acc[ms][ns][2]);
                C[(size_t)(r0 + 8) * ldc + c + 1] = __float2half(acc[ms][ns][3]);
            } else {
                float* C = (float*)Cv;
                C[(size_t)r0 * ldc + c]           = acc[ms][ns][0];
                C[(size_t)r0 * ldc + c + 1]       = acc[ms][ns][1];
                C[(size_t)(r0 + 8) * ldc + c]     = acc[ms][ns][2];
                C[(size_t)(r0 + 8) * ldc + c + 1] = acc[ms][ns][3];
            }
        }
    }
}

// ---------------- per-step elementwise kernel A: m4 + softmax mix -> msg -----------
__global__ void __launch_bounds__(128) step_msg(const float* __restrict__ m_seq,
                                                const float* __restrict__ tf_seq,
                                                const float* __restrict__ tj_seq,
                                                const float* __restrict__ b_msg,
                                                const float* __restrict__ mix_W,
                                                const float* __restrict__ mix_b,
                                                const float* __restrict__ path_bias,
                                                int t) {
    int n = blockIdx.x, j = threadIdx.x;
    float hj = d_hst[n * H_DIM + j];
    __shared__ float sred[128];
    __shared__ float slg[4];
#pragma unroll
    for (int p = 0; p < 4; p++) {
        sred[j] = hj * mix_W[p * H_DIM + j];
        __syncthreads();
        for (int o = 64; o > 0; o >>= 1) {
            if (j < o) sred[j] += sred[j + o];
            __syncthreads();
        }
        if (j == 0) slg[p] = sred[0] + mix_b[p] + path_bias[p];
        __syncthreads();
    }
    float lg0 = slg[0], lg1 = slg[1], lg2 = slg[2], lg3 = slg[3];
    float mx = fmaxf(fmaxf(lg0, lg1), fmaxf(lg2, lg3));
    float e0 = expf(lg0 - mx), e1 = expf(lg1 - mx), e2 = expf(lg2 - mx), e3 = expf(lg3 - mx);
    float inv = 1.f / (e0 + e1 + e2 + e3);
    float wp[4] = {e0 * inv, e1 * inv, e2 * inv, e3 * inv};

    float u[3], p1c[3], p2c[3];
    u[0] = m_seq[n * T_STEPS + t];
    u[1] = tf_seq[n * T_STEPS + t];
    u[2] = tj_seq[n * T_STEPS + t];
#pragma unroll
    for (int c = 0; c < 3; c++) {
        p1c[c] = __half2float(d_P1[n * 192 + c * 64 + t]);
        p2c[c] = __half2float(d_P2[n * 192 + c * 64 + t]);
    }
    float msg = 0.f;
#pragma unroll
    for (int p = 0; p < 4; p++) {
        float a = d_M4[(size_t)n * 512 + p * 128 + j] + b_msg[p * H_DIM + j];
#pragma unroll
        for (int c = 0; c < 3; c++) {
            a += u[c]   * d_WuC[((c * 3 + 0) * 4 + p) * 128 + j];
            a += p1c[c] * d_WuC[((c * 3 + 1) * 4 + p) * 128 + j];
            a += p2c[c] * d_WuC[((c * 3 + 2) * 4 + p) * 128 + j];
        }
        msg += wp[p] * tanhf(a);
    }
    d_X[n * 256 + j] = __float2half(msg);
}

// ---------------- per-step elementwise kernel B: GRU gates + skip + pred -----------
__global__ void __launch_bounds__(128) step_gru(const float* __restrict__ x_seq,
                                                const float* __restrict__ m_seq,
                                                const float* __restrict__ tf_seq,
                                                const float* __restrict__ tj_seq,
                                                const float* __restrict__ W_ih,
                                                const float* __restrict__ b_ih,
                                                const float* __restrict__ b_hh,
                                                const float* __restrict__ out_W,
                                                const float* __restrict__ out_b,
                                                float* __restrict__ out, int t) {
    int n = blockIdx.x, j = threadIdx.x;
    float x = x_seq[n * T_STEPS + t];
    float m = m_seq[n * T_STEPS + t];
    float tf = tf_seq[n * T_STEPS + t];
    float tj = tj_seq[n * T_STEPS + t];
    float h = d_hst[n * H_DIM + j];

    const float* ggn = d_GG + (size_t)n * 768;
    float gi[3], gh[3];
#pragma unroll
    for (int q = 0; q < 3; q++) {
        int r = q * 128 + j;
        const float* wr = W_ih + (size_t)r * GIN_ + 128;
        gi[q] = ggn[r] + x * wr[0] + m * wr[1] + tf * wr[2] + tj * wr[3] + b_ih[r];
        gh[q] = ggn[384 + r] + b_hh[r];
    }
    float rg = 1.f / (1.f + expf(-(gi[0] + gh[0])));
    float z  = 1.f / (1.f + expf(-(gi[1] + gh[1])));
    float nc = tanhf(gi[2] + rg * gh[2]);
    float hn = (1.f - z) * nc + z * h;
    float mp = __half2float(d_P1[n * 192 + t]) * d_Dfac[n];
    float skip = (0.1f + 0.05f * (1.f - m)) * (1.f - 0.3f * mp);
    float h2 = hn + skip * h;

    d_hst[n * H_DIM + j] = h2;
    __half hh = __float2half(h2);
    d_S[n * 384 + j] = hh;
    d_X[n * 256 + 128 + j] = hh;

    __shared__ float sred[128];
    sred[j] = h2 * out_W[j];
    __syncthreads();
    for (int o = 64; o > 0; o >>= 1) {
        if (j < o) sred[j] += sred[j + o];
        __syncthreads();
    }
    if (j == 0) out[n * T_STEPS + t] = sred[0] + out_b[0];
}

// ---------------- host launcher ----------------
extern "C" void kernel_launch(void* const* d_in, const int* in_sizes, int n_in,
                              void* d_out, int out_size) {
    const float* x_seq     = (const float*)d_in[0];
    const float* m_seq     = (const float*)d_in[1];
    const float* tf_seq    = (const float*)d_in[2];
    const float* tj_seq    = (const float*)d_in[3];
    const float* A         = (const float*)d_in[4];
    const float* W_msg     = (const float*)d_in[5];
    const float* b_msg     = (const float*)d_in[6];
    const float* path_bias = (const float*)d_in[7];
    const float* mix_W     = (const float*)d_in[8];
    const float* mix_b     = (const float*)d_in[9];
    const float* W_ih      = (const float*)d_in[10];
    const float* W_hh      = (const float*)d_in[11];
    const float* b_ih      = (const float*)d_in[12];
    const float* b_hh      = (const float*)d_in[13];
    const float* out_W     = (const float*)d_in[14];
    const float* out_b     = (const float*)d_in[15];
    float* out = (float*)d_out;

    void *pAh, *pU, *pP1, *pP2, *pS, *pX, *pM4, *pGG, *pWcat, *pWihm, *pWhh;
    cudaGetSymbolAddress(&pAh, d_Ah);
    cudaGetSymbolAddress(&pU, d_U16);
    cudaGetSymbolAddress(&pP1, d_P1);
    cudaGetSymbolAddress(&pP2, d_P2);
    cudaGetSymbolAddress(&pS, d_S);
    cudaGetSymbolAddress(&pX, d_X);
    cudaGetSymbolAddress(&pM4, d_M4);
    cudaGetSymbolAddress(&pGG, d_GG);
    cudaGetSymbolAddress(&pWcat, d_Wcat);
    cudaGetSymbolAddress(&pWihm, d_Wihm);
    cudaGetSymbolAddress(&pWhh, d_Whh);

    rownorm_kernel<<<N_NODES, 256>>>(A);
    build_u_kernel<<<(N_NODES * T_STEPS + 255) / 256, 256>>>(m_seq, tf_seq, tj_seq);
    build_w_kernel<<<(384 * 512 + 3 * 3 * 4 * 128 + 2 * 128 * 384 + 255) / 256, 256>>>(W_msg, W_ih, W_hh);
    init_kernel<<<(N_NODES * H_DIM + 255) / 256, 256>>>();

    // P1 = Anorm @ U, P2 = Anorm @ P1   (M=4096, N=192, K=4096)
    dim3 gP(192 / 64, N_NODES / 64);
    gemm_tc<true><<<gP, 128>>>((const __half*)pAh, (const __half*)pU, pP1,
                               N_NODES, 192, N_NODES, N_NODES, 192, 192);
    gemm_tc<true><<<gP, 128>>>((const __half*)pAh, (const __half*)pP1, pP2,
                               N_NODES, 192, N_NODES, N_NODES, 192, 192);

    dim3 g1(128 / 64, N_NODES / 64);   // big diffusion GEMMs
    dim3 g3(512 / 64, N_NODES / 64);   // M4 GEMM
    dim3 g4(384 / 64, N_NODES / 64);   // GRU GEMMs

    for (int t = 0; t < T_STEPS; t++) {
        // G1 = Anorm @ h   (into S cols 128..255)
        gemm_tc<true><<<g1, 128>>>((const __half*)pAh, (const __half*)pS,
                                   (void*)((__half*)pS + 128),
                                   N_NODES, 128, N_NODES, N_NODES, 384, 384);
        // G2 = Anorm @ G1  (into S cols 256..383)
        gemm_tc<true><<<g1, 128>>>((const __half*)pAh, (const __half*)((__half*)pS + 128),
                                   (void*)((__half*)pS + 256),
                                   N_NODES, 128, N_NODES, N_NODES, 384, 384);
        // M4pre = S @ Wcat  (N x 512, fp32)
        gemm_tc<false><<<g3, 128>>>((const __half*)pS, (const __half*)pWcat, pM4,
                                    N_NODES, 512, 384, 384, 512, 512);
        step_msg<<<N_NODES, 128>>>(m_seq, tf_seq, tj_seq, b_msg, mix_W, mix_b, path_bias, t);
        // gi_msg = msg @ W_ih[:, :128]^T  -> GG[:, 0:384]
        gemm_tc<false><<<g4, 128>>>((const __half*)pX, (const __half*)pWihm, pGG,
                                    N_NODES, 384, 128, 256, 384, 768);
        // gh = h @ W_hh^T -> GG[:, 384:768]
        gemm_tc<false><<<g4, 128>>>((const __half*)((__half*)pX + 128), (const __half*)pWhh,
                                    (void*)((float*)pGG + 384),
                                    N_NODES, 384, 128, 256, 384, 768);
        step_gru<<<N_NODES, 128>>>(x_seq, m_seq, tf_seq, tj_seq, W_ih, b_ih, b_hh,
                                   out_W, out_b, out, t);
    }
}

// round 5
// speedup vs baseline: 2.4522x; 2.4522x over previous
#include <cuda_runtime.h>
#include <cuda_fp16.h>
#include <cstdint>

#define N_NODES 4096
#define T_STEPS 64
#define H_DIM   128
#define DIN_    131
#define GIN_    132

// ---------------- static device workspace ----------------
__device__ __half d_Ah[(size_t)N_NODES * N_NODES];   // row-normalized A, fp16 (33.5 MB)
__device__ float  d_Dfac[N_NODES];                   // D/(D+1e-8)
__device__ __half d_U16[N_NODES * 256];              // [n][c*64+t], c=m,tf,tj; cols 192.. zero
__device__ __half d_P1[N_NODES * 256];               // Anorm @ U
__device__ __half d_P2[N_NODES * 256];               // Anorm @ P1
__device__ __half d_S[N_NODES * 384];                // [h | G1 | G2] fp16
__device__ __half d_X[N_NODES * 256];                // [msg | h] fp16
__device__ float  d_hst[N_NODES * H_DIM];            // carried state fp32 (exact)
__device__ float  d_M4[(size_t)N_NODES * 640];       // S @ Wcat (incl. mix logits at 512..515)
__device__ float  d_GG[(size_t)N_NODES * 768];       // [gi_msg | gh]
__device__ float  d_Part[(size_t)4 * N_NODES * 256]; // split-K partials (16.7 MB)
__device__ __half d_Wcat[384 * 640];                 // folded Cheb weights + mix cols
__device__ float  d_WuC[3 * 3 * 4 * H_DIM];          // folded Cheb weights (u part)
__device__ __half d_Wblk[256 * 768];                 // block-diag [Wihm ; Whh]

// ---------------- prep kernels ----------------
__global__ void __launch_bounds__(256) rownorm_kernel(const float* __restrict__ A) {
    int n = blockIdx.x;
    const float* row = A + (size_t)n * N_NODES;
    float s = 0.f;
    for (int j = threadIdx.x; j < N_NODES; j += 256) s += row[j];
    __shared__ float red[256];
    red[threadIdx.x] = s;
    __syncthreads();
    for (int o = 128; o > 0; o >>= 1) {
        if (threadIdx.x < o) red[threadIdx.x] += red[threadIdx.x + o];
        __syncthreads();
    }
    float D = red[0];
    float Dinv = (D > 0.f) ? (1.0f / D) : 0.f;
    if (threadIdx.x == 0) d_Dfac[n] = D / (D + 1e-8f);
    __half* dst = d_Ah + (size_t)n * N_NODES;
    for (int j = threadIdx.x; j < N_NODES; j += 256) dst[j] = __float2half(row[j] * Dinv);
}

__global__ void __launch_bounds__(256) build_u_kernel(const float* __restrict__ m,
                                                      const float* __restrict__ tf,
                                                      const float* __restrict__ tj) {
    int i = blockIdx.x * 256 + threadIdx.x;
    if (i >= N_NODES * 256) return;
    int n = i >> 8, c = i & 255;
    float v = 0.f;
    if (c < 64)        v = m[n * 64 + c];
    else if (c < 128)  v = tf[n * 64 + c - 64];
    else if (c < 192)  v = tj[n * 64 + c - 128];
    d_U16[i] = __float2half(v);
}

// W_msg layout: [4][3][131][128] : ((p*3+k)*131 + d)*128 + j
__global__ void __launch_bounds__(256) build_w_kernel(const float* __restrict__ W_msg,
                                                      const float* __restrict__ W_ih,
                                                      const float* __restrict__ W_hh,
                                                      const float* __restrict__ mix_W) {
    int i = blockIdx.x * 256 + threadIdx.x;
    const int NWCAT = 384 * 640;
    const int NWUC  = 3 * 3 * 4 * 128;
    const int NWBLK = 256 * 768;
    if (i < NWCAT) {
        int d = i / 640, q = i - d * 640;
        float v = 0.f;
        if (q < 512) {
            int p = q >> 7, j = q & 127;
            int kc = d >> 7, c = d & 127;
            if (kc == 0)      v = W_msg[((p*3+0)*DIN_ + c)*128 + j] - W_msg[((p*3+2)*DIN_ + c)*128 + j];
            else if (kc == 1) v = W_msg[((p*3+1)*DIN_ + c)*128 + j];
            else              v = 2.f * W_msg[((p*3+2)*DIN_ + c)*128 + j];
        } else if (q < 516 && d < 128) {
            v = mix_W[(q - 512) * 128 + d];
        }
        d_Wcat[i] = __float2half(v);
    } else if (i < NWCAT + NWUC) {
        int r = i - NWCAT;
        int j = r & 127;
        int p = (r >> 7) & 3;
        int t2 = r >> 9;          // 0..8 = c*3 + which
        int which = t2 % 3;
        int c = t2 / 3;
        int dd = 128 + c;
        float v;
        if (which == 0)      v = W_msg[((p*3+0)*DIN_ + dd)*128 + j] - W_msg[((p*3+2)*DIN_ + dd)*128 + j];
        else if (which == 1) v = W_msg[((p*3+1)*DIN_ + dd)*128 + j];
        else                 v = 2.f * W_msg[((p*3+2)*DIN_ + dd)*128 + j];
        d_WuC[r] = v;
    } else if (i < NWCAT + NWUC + NWBLK) {
        int r = i - (NWCAT + NWUC);
        int d = r / 768, c = r - d * 768;
        float v = 0.f;
        if (d < 128) {
            if (c < 384) v = W_ih[(size_t)c * GIN_ + d];      // gi = msg @ W_ih[:, :128]^T
        } else {
            if (c >= 384) v = W_hh[(size_t)(c - 384) * 128 + (d - 128)];  // gh = h @ W_hh^T
        }
        d_Wblk[r] = __float2half(v);
    }
}

__global__ void __launch_bounds__(256) init_kernel() {
    int i = blockIdx.x * 256 + threadIdx.x;
    if (i >= N_NODES * H_DIM) return;
    int n = i >> 7, j = i & 127;
    d_hst[i] = 0.f;
    d_S[n * 384 + j] = __float2half(0.f);
    d_X[n * 256 + 128 + j] = __float2half(0.f);
}

// ---------------- pipelined fp16 TC GEMM: C[M,Nc] = A[M,K] @ B[K,Nc] ---------------
// BM=128, BN=128, BK=32, 2-stage cp.async double buffer, 256 threads (8 warps, 32x64 each).
// grid = (Nc/128, M/128, SPLIT).  SPLIT>1 -> write fp32 partial slab per split.
#define CPA16(dst, src) asm volatile("cp.async.cg.shared.global [%0], [%1], 16;\n" :: "r"(dst), "l"(src))
#define CPCOMMIT() asm volatile("cp.async.commit_group;\n" ::)

template <int SPLIT>
__global__ void __launch_bounds__(256) gemmP(const __half* __restrict__ Ag, int lda,
                                             const __half* __restrict__ Bg, int ldb,
                                             float* __restrict__ Cg, int ldc, int K) {
    __shared__ __half sA[2][128][40];
    __shared__ __half sB[2][32][136];
    const int tid = threadIdx.x;
    const int lane = tid & 31, w = tid >> 5;
    const int wm = w >> 1, wn = w & 1;
    const int g = lane >> 2, tig = lane & 3;
    const int lm = lane & 15, hi = lane >> 4;
    const int row0 = blockIdx.y * 128;
    const int col0 = blockIdx.x * 128;
    const int Kc = K / SPLIT;
    const int kbase = blockIdx.z * Kc;
    const int NIT = Kc / 32;
    if (SPLIT > 1) Cg += (size_t)blockIdx.z * ((size_t)gridDim.y * 128) * ldc;

    uint32_t sAb = (uint32_t)__cvta_generic_to_shared(&sA[0][0][0]);
    uint32_t sBb = (uint32_t)__cvta_generic_to_shared(&sB[0][0][0]);

    float acc[2][8][4];
#pragma unroll
    for (int a = 0; a < 2; a++)
#pragma unroll
        for (int b = 0; b < 8; b++)
#pragma unroll
            for (int c = 0; c < 4; c++) acc[a][b][c] = 0.f;

    auto load_stage = [&](int s, int it) {
        int kg = kbase + it * 32;
        uint32_t aS = sAb + s * 10240;
        uint32_t bS = sBb + s * 8704;
#pragma unroll
        for (int ch = tid; ch < 512; ch += 256) {
            int r = ch >> 2, c = (ch & 3) << 3;
            const __half* src = Ag + (size_t)(row0 + r) * lda + kg + c;
            CPA16(aS + (uint32_t)(r * 40 + c) * 2, src);
        }
#pragma unroll
        for (int ch = tid; ch < 512; ch += 256) {
            int r = ch >> 4, c = (ch & 15) << 3;
            const __half* src = Bg + (size_t)(kg + r) * ldb + col0 + c;
            CPA16(bS + (uint32_t)(r * 136 + c) * 2, src);
        }
    };

    load_stage(0, 0);
    CPCOMMIT();

    for (int it = 0; it < NIT; it++) {
        if (it + 1 < NIT) {
            load_stage((it + 1) & 1, it + 1);
            CPCOMMIT();
            asm volatile("cp.async.wait_group 1;\n" ::);
        } else {
            asm volatile("cp.async.wait_group 0;\n" ::);
        }
        __syncthreads();

        int s = it & 1;
        uint32_t aS = sAb + s * 10240;
        uint32_t bS = sBb + s * 8704;
#pragma unroll
        for (int ks = 0; ks < 2; ks++) {
            int kk = ks * 16;
            uint32_t Af[2][4];
#pragma unroll
            for (int ms = 0; ms < 2; ms++) {
                int rm = wm * 32 + ms * 16;
                uint32_t addr = aS + (uint32_t)((rm + lm) * 40 + kk + hi * 8) * 2;
                asm volatile("ldmatrix.sync.aligned.m8n8.x4.shared.b16 {%0,%1,%2,%3},[%4];\n"
                             : "=r"(Af[ms][0]), "=r"(Af[ms][1]), "=r"(Af[ms][2]), "=r"(Af[ms][3])
                             : "r"(addr));
            }
            uint32_t Bf[8][2];
#pragma unroll
            for (int nb = 0; nb < 4; nb++) {
                int cn = wn * 64 + nb * 16;
                uint32_t r0, r1, r2, r3;
                uint32_t addr = bS + (uint32_t)((kk + lm) * 136 + cn + hi * 8) * 2;
                asm volatile("ldmatrix.sync.aligned.m8n8.x4.trans.shared.b16 {%0,%1,%2,%3},[%4];\n"
                             : "=r"(r0), "=r"(r1), "=r"(r2), "=r"(r3) : "r"(addr));
                Bf[2*nb][0] = r0; Bf[2*nb][1] = r1;
                Bf[2*nb+1][0] = r2; Bf[2*nb+1][1] = r3;
            }
#pragma unroll
            for (int ms = 0; ms < 2; ms++)
#pragma unroll
                for (int ns = 0; ns < 8; ns++)
                    asm volatile(
                        "mma.sync.aligned.m16n8k16.row.col.f32.f16.f16.f32 "
                        "{%0,%1,%2,%3},{%4,%5,%6,%7},{%8,%9},{%0,%1,%2,%3};\n"
                        : "+f"(acc[ms][ns][0]), "+f"(acc[ms][ns][1]),
                          "+f"(acc[ms][ns][2]), "+f"(acc[ms][ns][3])
                        : "r"(Af[ms][0]), "r"(Af[ms][1]), "r"(Af[ms][2]), "r"(Af[ms][3]),
                          "r"(Bf[ns][0]), "r"(Bf[ns][1]));
        }
        __syncthreads();
    }

#pragma unroll
    for (int ms = 0; ms < 2; ms++) {
        int r = row0 + wm * 32 + ms * 16 + g;
#pragma unroll
        for (int ns = 0; ns < 8; ns++) {
            int c = col0 + wn * 64 + ns * 8 + tig * 2;
            *(float2*)&Cg[(size_t)r * ldc + c]       = make_float2(acc[ms][ns][0], acc[ms][ns][1]);
            *(float2*)&Cg[(size_t)(r + 8) * ldc + c] = make_float2(acc[ms][ns][2], acc[ms][ns][3]);
        }
    }
}

// ---------------- split-K reduce: sum 4 fp32 partials -> fp16 out --------------
__global__ void __launch_bounds__(256) reduce4(const float* __restrict__ part, int W,
                                               __half* __restrict__ out, int ldo, int off) {
    int i = blockIdx.x * 256 + threadIdx.x;
    int W2 = W >> 1;
    if (i >= N_NODES * W2) return;
    int n = i / W2;
    int c2 = (i - n * W2) * 2;
    size_t stride = (size_t)N_NODES * W;
    const float* p = part + (size_t)n * W + c2;
    float2 s = *(const float2*)p;
    float2 b = *(const float2*)(p + stride);     s.x += b.x; s.y += b.y;
    b = *(const float2*)(p + 2 * stride);        s.x += b.x; s.y += b.y;
    b = *(const float2*)(p + 3 * stride);        s.x += b.x; s.y += b.y;
    *(__half2*)&out[(size_t)n * ldo + off + c2] = __floats2half2_rn(s.x, s.y);
}

// ---------------- per-step elementwise A: m4 + softmax mix -> msg ---------------
__global__ void __launch_bounds__(256) step_msg(const float* __restrict__ m_seq,
                                                const float* __restrict__ tf_seq,
                                                const float* __restrict__ tj_seq,
                                                const float* __restrict__ b_msg,
                                                const float* __restrict__ mix_b,
                                                const float* __restrict__ path_bias,
                                                int t) {
    int i = blockIdx.x * 256 + threadIdx.x;
    if (i >= N_NODES * H_DIM) return;
    int n = i >> 7, j = i & 127;
    const float* m4n = d_M4 + (size_t)n * 640;

    float lg[4];
#pragma unroll
    for (int p = 0; p < 4; p++) lg[p] = m4n[512 + p] + mix_b[p] + path_bias[p];
    float mx = fmaxf(fmaxf(lg[0], lg[1]), fmaxf(lg[2], lg[3]));
    float e0 = expf(lg[0] - mx), e1 = expf(lg[1] - mx), e2 = expf(lg[2] - mx), e3 = expf(lg[3] - mx);
    float inv = 1.f / (e0 + e1 + e2 + e3);
    float wp[4] = {e0 * inv, e1 * inv, e2 * inv, e3 * inv};

    float u[3], p1c[3], p2c[3];
    u[0] = m_seq[n * T_STEPS + t];
    u[1] = tf_seq[n * T_STEPS + t];
    u[2] = tj_seq[n * T_STEPS + t];
#pragma unroll
    for (int c = 0; c < 3; c++) {
        p1c[c] = __half2float(d_P1[n * 256 + c * 64 + t]);
        p2c[c] = __half2float(d_P2[n * 256 + c * 64 + t]);
    }
    float msg = 0.f;
#pragma unroll
    for (int p = 0; p < 4; p++) {
        float a = m4n[p * 128 + j] + b_msg[p * H_DIM + j];
#pragma unroll
        for (int c = 0; c < 3; c++) {
            a += u[c]   * d_WuC[((c * 3 + 0) * 4 + p) * 128 + j];
            a += p1c[c] * d_WuC[((c * 3 + 1) * 4 + p) * 128 + j];
            a += p2c[c] * d_WuC[((c * 3 + 2) * 4 + p) * 128 + j];
        }
        msg += wp[p] * tanhf(a);
    }
    d_X[n * 256 + j] = __float2half(msg);
}

// ---------------- per-step elementwise B: GRU gates + skip + pred ---------------
__global__ void __launch_bounds__(128) step_gru(const float* __restrict__ x_seq,
                                                const float* __restrict__ m_seq,
                                                const float* __restrict__ tf_seq,
                                                const float* __restrict__ tj_seq,
                                                const float* __restrict__ W_ih,
                                                const float* __restrict__ b_ih,
                                                const float* __restrict__ b_hh,
                                                const float* __restrict__ out_W,
                                                const float* __restrict__ out_b,
                                                float* __restrict__ out, int t) {
    int n = blockIdx.x, j = threadIdx.x;
    float x = x_seq[n * T_STEPS + t];
    float m = m_seq[n * T_STEPS + t];
    float tf = tf_seq[n * T_STEPS + t];
    float tj = tj_seq[n * T_STEPS + t];
    float h = d_hst[n * H_DIM + j];

    const float* ggn = d_GG + (size_t)n * 768;
    float gi[3], gh[3];
#pragma unroll
    for (int q = 0; q < 3; q++) {
        int r = q * 128 + j;
        const float* wr = W_ih + (size_t)r * GIN_ + 128;
        gi[q] = ggn[r] + x * wr[0] + m * wr[1] + tf * wr[2] + tj * wr[3] + b_ih[r];
        gh[q] = ggn[384 + r] + b_hh[r];
    }
    float rg = 1.f / (1.f + expf(-(gi[0] + gh[0])));
    float z  = 1.f / (1.f + expf(-(gi[1] + gh[1])));
    float nc = tanhf(gi[2] + rg * gh[2]);
    float hn = (1.f - z) * nc + z * h;
    float mp = __half2float(d_P1[n * 256 + t]) * d_Dfac[n];
    float skip = (0.1f + 0.05f * (1.f - m)) * (1.f - 0.3f * mp);
    float h2 = hn + skip * h;

    d_hst[n * H_DIM + j] = h2;
    __half hh = __float2half(h2);
    d_S[n * 384 + j] = hh;
    d_X[n * 256 + 128 + j] = hh;

    __shared__ float sred[128];
    sred[j] = h2 * out_W[j];
    __syncthreads();
    for (int o = 64; o > 0; o >>= 1) {
        if (j < o) sred[j] += sred[j + o];
        __syncthreads();
    }
    if (j == 0) out[n * T_STEPS + t] = sred[0] + out_b[0];
}

// ---------------- host launcher ----------------
extern "C" void kernel_launch(void* const* d_in, const int* in_sizes, int n_in,
                              void* d_out, int out_size) {
    const float* x_seq     = (const float*)d_in[0];
    const float* m_seq     = (const float*)d_in[1];
    const float* tf_seq    = (const float*)d_in[2];
    const float* tj_seq    = (const float*)d_in[3];
    const float* A         = (const float*)d_in[4];
    const float* W_msg     = (const float*)d_in[5];
    const float* b_msg     = (const float*)d_in[6];
    const float* path_bias = (const float*)d_in[7];
    const float* mix_W     = (const float*)d_in[8];
    const float* mix_b     = (const float*)d_in[9];
    const float* W_ih      = (const float*)d_in[10];
    const float* W_hh      = (const float*)d_in[11];
    const float* b_ih      = (const float*)d_in[12];
    const float* b_hh      = (const float*)d_in[13];
    const float* out_W     = (const float*)d_in[14];
    const float* out_b     = (const float*)d_in[15];
    float* out = (float*)d_out;

    void *pAh, *pU, *pP1, *pP2, *pS, *pX, *pM4, *pGG, *pPart, *pWcat, *pWblk;
    cudaGetSymbolAddress(&pAh, d_Ah);
    cudaGetSymbolAddress(&pU, d_U16);
    cudaGetSymbolAddress(&pP1, d_P1);
    cudaGetSymbolAddress(&pP2, d_P2);
    cudaGetSymbolAddress(&pS, d_S);
    cudaGetSymbolAddress(&pX, d_X);
    cudaGetSymbolAddress(&pM4, d_M4);
    cudaGetSymbolAddress(&pGG, d_GG);
    cudaGetSymbolAddress(&pPart, d_Part);
    cudaGetSymbolAddress(&pWcat, d_Wcat);
    cudaGetSymbolAddress(&pWblk, d_Wblk);

    rownorm_kernel<<<N_NODES, 256>>>(A);
    build_u_kernel<<<(N_NODES * 256 + 255) / 256, 256>>>(m_seq, tf_seq, tj_seq);
    build_w_kernel<<<(384*640 + 3*3*4*128 + 256*768 + 255) / 256, 256>>>(W_msg, W_ih, W_hh, mix_W);
    init_kernel<<<(N_NODES * H_DIM + 255) / 256, 256>>>();

    // P1 = Anorm @ U, P2 = Anorm @ P1  (Nc=256 padded, split-K=4)
    gemmP<4><<<dim3(2, 32, 4), 256>>>((const __half*)pAh, N_NODES, (const __half*)pU, 256,
                                      (float*)pPart, 256, N_NODES);
    reduce4<<<(N_NODES * 128 + 255) / 256, 256>>>((const float*)pPart, 256, (__half*)pP1, 256, 0);
    gemmP<4><<<dim3(2, 32, 4), 256>>>((const __half*)pAh, N_NODES, (const __half*)pP1, 256,
                                      (float*)pPart, 256, N_NODES);
    reduce4<<<(N_NODES * 128 + 255) / 256, 256>>>((const float*)pPart, 256, (__half*)pP2, 256, 0);

    for (int t = 0; t < T_STEPS; t++) {
        // G1 = Anorm @ h -> S cols 128..255
        gemmP<4><<<dim3(1, 32, 4), 256>>>((const __half*)pAh, N_NODES, (const __half*)pS, 384,
                                          (float*)pPart, 128, N_NODES);
        reduce4<<<(N_NODES * 64 + 255) / 256, 256>>>((const float*)pPart, 128, (__half*)pS, 384, 128);
        // G2 = Anorm @ G1 -> S cols 256..383
        gemmP<4><<<dim3(1, 32, 4), 256>>>((const __half*)pAh, N_NODES,
                                          (const __half*)pS + 128, 384,
                                          (float*)pPart, 128, N_NODES);
        reduce4<<<(N_NODES * 64 + 255) / 256, 256>>>((const float*)pPart, 128, (__half*)pS, 384, 256);
        // M4pre (+ mix logits) = S @ Wcat  -> d_M4 [4096 x 640] fp32
        gemmP<1><<<dim3(5, 32, 1), 256>>>((const __half*)pS, 384, (const __half*)pWcat, 640,
                                          (float*)pM4, 640, 384);
        step_msg<<<(N_NODES * H_DIM + 255) / 256, 256>>>(m_seq, tf_seq, tj_seq, b_msg, mix_b, path_bias, t);
        // [gi_msg | gh] = X @ Wblk -> d_GG [4096 x 768] fp32
        gemmP<1><<<dim3(6, 32, 1), 256>>>((const __half*)pX, 256, (const __half*)pWblk, 768,
                                          (float*)pGG, 768, 256);
        step_gru<<<N_NODES, 128>>>(x_seq, m_seq, tf_seq, tj_seq, W_ih, b_ih, b_hh,
                                   out_W, out_b, out, t);
    }
}